// round 5
// baseline (speedup 1.0000x reference)
#include <cuda_runtime.h>
#include <cstddef>

// Butterfly n=1024, log_n=10, increasing stride, + bias. 32768 rows.
//
// R5: transpose formulation. Stages 0-4 (strides 1..16) in-warp via shfl.
// ONE smem 32x32 transpose (pad-33, conflict-free) maps strides 32..512 to
// strides 1..16, so stages 5-9 are ALSO in-warp shfl. Final values are in
// transposed layout -> one smem out-staging pass restores coalesced STG.64.
// Barriers per 2-row iteration: 4 -> 2. Twiddles for the transposed stages
// use a static per-thread index mapping (trans pair k -> orig pair p),
// with the validated rsw/csw pre-permutation applied in trans space.
// 2-row ILP + prefetch. No double buffering needed: the two barriers
// mutually order buffer reuse across iterations.

constexpr int TPB  = 512;
constexpr int GRID = 296;

__global__ __launch_bounds__(TPB, 2)
void butterfly_kernel(const float* __restrict__ x,
                      const float* __restrict__ tw,
                      const float* __restrict__ bias,
                      float* __restrict__ out,
                      int nrows)
{
    __shared__ float TB[2][1056];   // transpose buffers (pad: phys = e + (e>>5))
    __shared__ float OB[2][1056];   // output staging buffers
    const int k = threadIdx.x;      // pair slot 0..511
    const int l = k & 31;
    const int w = k >> 5;

    // ---- twiddles with steering pre-permutation ----------------------------
    const float4* tw4 = reinterpret_cast<const float4*>(tw);
    float4 T[10];
#pragma unroll
    for (int j = 0; j < 5; ++j) {               // stages 0-4: orig pair index = k
        float4 t = tw4[j * 512 + k];
        const bool rsw = ((k >> j) & 1) != 0;                    // keep/send rows
        const bool csw = (j >= 1) && (((k >> (j - 1)) & 1) != 0);// input orientation
        if (rsw) t = make_float4(t.z, t.w, t.x, t.y);
        if (csw) t = make_float4(t.y, t.x, t.w, t.z);
        T[j] = t;
    }
#pragma unroll
    for (int j2 = 0; j2 < 5; ++j2) {            // trans stages 0-4 = orig 5-9
        const int j  = j2 + 5;
        const int f0 = ((k >> j2) << (j2 + 1)) | (k & ((1 << j2) - 1));
        const int e0 = ((f0 & 31) << 5) | (f0 >> 5);             // invT
        const int p  = ((e0 >> (j + 1)) << j) | (e0 & ((1 << j) - 1));
        float4 t = tw4[j * 512 + p];
        const bool rsw = (j2 <= 3) && (((k >> j2) & 1) != 0);
        const bool csw = (j2 >= 1) && (((k >> (j2 - 1)) & 1) != 0);
        if (rsw) t = make_float4(t.z, t.w, t.x, t.y);
        if (csw) t = make_float4(t.y, t.x, t.w, t.z);
        T[5 + j2] = t;
    }

    // ---- static smem addresses ---------------------------------------------
    // transpose store: entering "stage 5", (P,Q) = elements (e0, e0+32) of the
    // original row (swapped if bit4(k)). Trans targets: T(e0)=(l<<5)|(w<<1), +1.
    const int Te0   = (l << 5) | (w << 1);
    const int sw5   = (k >> 4) & 1;
    const int physP = Te0 + l + sw5;            // pad-33: phys = e + (e>>5); (e>>5)=l
    const int physQ = Te0 + l + (1 - sw5);
    // transpose load: trans pair k = trans elements (2k, 2k+1)
    const int physL = 2 * k + ((2 * k) >> 5);   // +1 for the second element
    // out staging store: z0 -> orig elem e0o, z1 -> e0o+512
    const int e0o  = ((k & 15) << 5) | (k >> 4);
    const int pO0  = e0o + (k & 15);            // (e0o>>5) = k&15
    const int pO1  = pO0 + 528;                 // +512 + 16 rows of pad
    // out staging load: elements (2k, 2k+1) -> float2 -> coalesced STG.64

    const float bias0 = bias[e0o];
    const float bias1 = bias[e0o + 512];

    const float2* x2 = reinterpret_cast<const float2*>(x);
    const int npairs = (nrows + 1) >> 1;

    int pi = blockIdx.x;
    float2 A0 = make_float2(0.f, 0.f), A1 = A0;
    if (pi < npairs) {
        const int r0 = 2 * pi, r1 = 2 * pi + 1;
        A0 = x2[(size_t)r0 * 512 + k];
        if (r1 < nrows) A1 = x2[(size_t)r1 * 512 + k];
    }

    while (pi < npairs) {
        const int npi = pi + GRID;
        float2 NA0 = make_float2(0.f, 0.f), NA1 = NA0;
        if (npi < npairs) {                       // prefetch next row pair
            const int r0 = 2 * npi, r1 = 2 * npi + 1;
            NA0 = x2[(size_t)r0 * 512 + k];
            if (r1 < nrows) NA1 = x2[(size_t)r1 * 512 + k];
        }

        float P0 = A0.x, Q0 = A0.y;   // row 0
        float P1 = A1.x, Q1 = A1.y;   // row 1

        // ---- stages 0-4: compute + in-warp exchange (d = 1,2,4,8,16) ------
#pragma unroll
        for (int j = 0; j < 5; ++j) {
            float S0 = fmaf(T[j].z, P0, T[j].w * Q0);
            P0       = fmaf(T[j].x, P0, T[j].y * Q0);
            float S1 = fmaf(T[j].z, P1, T[j].w * Q1);
            P1       = fmaf(T[j].x, P1, T[j].y * Q1);
            const int d = 1 << j;
            Q0 = __shfl_xor_sync(0xffffffffu, S0, d);
            Q1 = __shfl_xor_sync(0xffffffffu, S1, d);
        }

        // ---- 32x32 transpose through smem ---------------------------------
        TB[0][physP] = P0;  TB[0][physQ] = Q0;
        TB[1][physP] = P1;  TB[1][physQ] = Q1;
        __syncthreads();
        P0 = TB[0][physL];  Q0 = TB[0][physL + 1];
        P1 = TB[1][physL];  Q1 = TB[1][physL + 1];

        // ---- stages 5-8 (trans 0-3): compute + in-warp exchange (d=1..8) --
#pragma unroll
        for (int j2 = 0; j2 < 4; ++j2) {
            const float4 t = T[5 + j2];
            float S0 = fmaf(t.z, P0, t.w * Q0);
            P0       = fmaf(t.x, P0, t.y * Q0);
            float S1 = fmaf(t.z, P1, t.w * Q1);
            P1       = fmaf(t.x, P1, t.y * Q1);
            const int d = 1 << j2;
            Q0 = __shfl_xor_sync(0xffffffffu, S0, d);
            Q1 = __shfl_xor_sync(0xffffffffu, S1, d);
        }

        // ---- stage 9 (trans 4, no exchange) + bias -------------------------
        const float z00 = fmaf(T[9].x, P0, fmaf(T[9].y, Q0, bias0));
        const float z10 = fmaf(T[9].z, P0, fmaf(T[9].w, Q0, bias1));
        const float z01 = fmaf(T[9].x, P1, fmaf(T[9].y, Q1, bias0));
        const float z11 = fmaf(T[9].z, P1, fmaf(T[9].w, Q1, bias1));

        // ---- out staging: un-transpose through smem, coalesced STG.64 -----
        OB[0][pO0] = z00;  OB[0][pO1] = z10;
        OB[1][pO0] = z01;  OB[1][pO1] = z11;
        __syncthreads();

        const int r0 = 2 * pi, r1 = 2 * pi + 1;
        {
            float2 v = make_float2(OB[0][physL], OB[0][physL + 1]);
            reinterpret_cast<float2*>(out + (size_t)r0 * 1024)[k] = v;
        }
        if (r1 < nrows) {
            float2 v = make_float2(OB[1][physL], OB[1][physL + 1]);
            reinterpret_cast<float2*>(out + (size_t)r1 * 1024)[k] = v;
        }

        pi = npi;
        A0 = NA0; A1 = NA1;
    }
}

extern "C" void kernel_launch(void* const* d_in, const int* in_sizes, int n_in,
                              void* d_out, int out_size)
{
    const float* x  = nullptr;
    const float* tw = nullptr;
    const float* bs = nullptr;
    long long x_elems = 0;
    for (int i = 0; i < n_in; ++i) {
        if (in_sizes[i] == 20480)     tw = (const float*)d_in[i];
        else if (in_sizes[i] == 1024) bs = (const float*)d_in[i];
        else { x = (const float*)d_in[i]; x_elems = in_sizes[i]; }
    }
    const int nrows = (int)(x_elems / 1024);

    butterfly_kernel<<<GRID, TPB>>>(x, tw, bs, (float*)d_out, nrows);
}

// round 6
// speedup vs baseline: 1.1360x; 1.1360x over previous
#include <cuda_runtime.h>
#include <cstddef>

// Butterfly n=1024, log_n=10, increasing stride, + bias. 32768 rows.
//
// R6: radix-4. Stages fused in pairs (0,1)(2,3)(4,5)(6,7)(8,9) into dense
// per-thread 4x4 matrices (product of two 2x2-block stage matrices has
// exactly 4 nonzeros/row => zero extra FLOPs), precomputed at init.
// 256 threads x 4 elements. Ownership per phase:
//   P0 {4t+m} (LDG.128) -> T1 lane-transpose xor(1,2) -> P1 {g1+4m}
//   -> T2 lane-transpose xor(4,8) -> P2 {g2+16m} -> T3 smem -> P3 {g3+64m}
//   -> T4 smem -> P4 {t+256m} -> +bias -> 4x coalesced STG.32.
// Lane-transposes: 4 shfl_xor each, zero selects: slot-steering permutations
// are folded into adjacent matrices' rows/cols (static per thread).
// T3/T4 smem layouts are conflict-free by construction (store banks r+16e,
// load banks t&31). 2 barriers/iter; buffer reuse ordered by bar alternation.

constexpr int TPB  = 256;
constexpr int GRID = 296;

__device__ __forceinline__ int pair_idx(int e, int j) {
    return ((e >> (j + 1)) << j) | (e & ((1 << j) - 1));
}

__device__ __forceinline__ float dot4(float4 m, float v0, float v1, float v2, float v3) {
    return fmaf(m.x, v0, fmaf(m.y, v1, fmaf(m.z, v2, m.w * v3)));
}

__global__ __launch_bounds__(TPB, 2)
void butterfly_kernel(const float* __restrict__ x,
                      const float* __restrict__ tw,
                      const float* __restrict__ bias,
                      float* __restrict__ out, int nrows)
{
    __shared__ float S3[2 * 1264];   // T3 buffers (addr = x + 16*(x>>6))
    __shared__ float S4[2 * 1056];   // T4 buffers (addr = x + (x>>5))
    const int t  = threadIdx.x;
    const int b0 = t & 1, b1 = (t >> 1) & 1, b2 = (t >> 2) & 1, b3 = (t >> 3) & 1;

    const int g1 = 16 * (t >> 2) + (t & 3);
    const int g2 = 64 * (t >> 4) + (t & 15);
    const int g3 = 256 * (t >> 6) + (t & 63);
    const int gbase[5] = { 4 * t, g1, g2, g3, t };

    // ---- build per-thread fused 4x4 matrices, with permutation folding ----
    float4 M[5][4];
    const float4* tw4 = reinterpret_cast<const float4*>(tw);
#pragma unroll
    for (int p = 0; p < 5; ++p) {
        const int j = 2 * p, s = 1 << j;
        const int G = gbase[p];
        const float4 pa = tw4[ j      * 512 + pair_idx(G,         j)];
        const float4 pb = tw4[ j      * 512 + pair_idx(G + 2 * s, j)];
        const float4 qa = tw4[(j + 1) * 512 + pair_idx(G,         j + 1)];
        const float4 qb = tw4[(j + 1) * 512 + pair_idx(G + s,     j + 1)];
        float4 R[4];
        R[0] = make_float4(qa.x * pa.x, qa.x * pa.y, qa.y * pb.x, qa.y * pb.y);
        R[1] = make_float4(qb.x * pa.z, qb.x * pa.w, qb.y * pb.z, qb.y * pb.w);
        R[2] = make_float4(qa.z * pa.x, qa.z * pa.y, qa.w * pb.x, qa.w * pb.y);
        R[3] = make_float4(qb.z * pa.z, qb.z * pa.w, qb.w * pb.z, qb.w * pb.w);

        // column fold: input slots arrive permuted from the previous transpose
        int cb0 = -1, cb1 = 0;
        if (p == 1) { cb0 = b0; cb1 = b1; }
        if (p == 2) { cb0 = b2; cb1 = b3; }
        if (cb0 >= 0) {
#pragma unroll
            for (int i = 0; i < 4; ++i) {
                const float c[4] = { R[i].x, R[i].y, R[i].z, R[i].w };
                float o[4];
#pragma unroll
                for (int sg = 0; sg < 4; ++sg)
                    o[sg] = c[(cb0 ^ (sg >> 1)) | ((cb1 ^ (sg & 1)) << 1)];
                R[i] = make_float4(o[0], o[1], o[2], o[3]);
            }
        }
        // row fold: outputs placed so the next transpose sends fixed slots
        int rb0 = -1, rb1 = 0;
        if (p == 0) { rb0 = b0; rb1 = b1; }
        if (p == 1) { rb0 = b2; rb1 = b3; }
        if (rb0 >= 0) {
            float4 Rp[4];
#pragma unroll
            for (int sg = 0; sg < 4; ++sg)
                Rp[sg] = R[(rb0 ^ (sg >> 1)) | ((rb1 ^ (sg & 1)) << 1)];
#pragma unroll
            for (int sg = 0; sg < 4; ++sg) R[sg] = Rp[sg];
        }
#pragma unroll
        for (int i = 0; i < 4; ++i) M[p][i] = R[i];
    }

    const float bz0 = bias[t], bz1 = bias[t + 256],
                bz2 = bias[t + 512], bz3 = bias[t + 768];

    // smem address bases (float units); all patterns bank-conflict-free
    const int a3s = g2 + 16 * (t >> 4);          // store: +16*m
    const int a3l = 320 * (t >> 6) + (t & 63);   // load:  +80*m
    const int a4s = g3 + (g3 >> 5);              // store: +66*m
    const int a4l = t + (t >> 5);                // load:  +264*m

    const float4* x4 = reinterpret_cast<const float4*>(x);
    const int npairs = (nrows + 1) >> 1;

    int pi = blockIdx.x;
    float4 A0 = make_float4(0.f,0.f,0.f,0.f), A1 = A0;
    if (pi < npairs) {
        A0 = x4[(size_t)(2 * pi) * 256 + t];
        if (2 * pi + 1 < nrows) A1 = x4[(size_t)(2 * pi + 1) * 256 + t];
    }

    while (pi < npairs) {
        const int npi = pi + GRID;
        float4 NA0 = make_float4(0.f,0.f,0.f,0.f), NA1 = NA0;
        if (npi < npairs) {                       // prefetch next row pair
            NA0 = x4[(size_t)(2 * npi) * 256 + t];
            if (2 * npi + 1 < nrows) NA1 = x4[(size_t)(2 * npi + 1) * 256 + t];
        }

        float u0 = A0.x, u1 = A0.y, u2 = A0.z, u3 = A0.w;   // row 0
        float w0 = A1.x, w1 = A1.y, w2 = A1.z, w3 = A1.w;   // row 1

        // ---- P0 (stages 0,1) ----
        float z0 = dot4(M[0][0], u0,u1,u2,u3), z1 = dot4(M[0][1], u0,u1,u2,u3),
              z2 = dot4(M[0][2], u0,u1,u2,u3), z3 = dot4(M[0][3], u0,u1,u2,u3);
        float y0 = dot4(M[0][0], w0,w1,w2,w3), y1 = dot4(M[0][1], w0,w1,w2,w3),
              y2 = dot4(M[0][2], w0,w1,w2,w3), y3 = dot4(M[0][3], w0,w1,w2,w3);
        // ---- T1: lane transpose over bits (0,1) ----
        z2 = __shfl_xor_sync(~0u, z2, 1);  z3 = __shfl_xor_sync(~0u, z3, 1);
        y2 = __shfl_xor_sync(~0u, y2, 1);  y3 = __shfl_xor_sync(~0u, y3, 1);
        z1 = __shfl_xor_sync(~0u, z1, 2);  z3 = __shfl_xor_sync(~0u, z3, 2);
        y1 = __shfl_xor_sync(~0u, y1, 2);  y3 = __shfl_xor_sync(~0u, y3, 2);
        // ---- P1 (stages 2,3) ----
        u0 = dot4(M[1][0], z0,z1,z2,z3);  u1 = dot4(M[1][1], z0,z1,z2,z3);
        u2 = dot4(M[1][2], z0,z1,z2,z3);  u3 = dot4(M[1][3], z0,z1,z2,z3);
        w0 = dot4(M[1][0], y0,y1,y2,y3);  w1 = dot4(M[1][1], y0,y1,y2,y3);
        w2 = dot4(M[1][2], y0,y1,y2,y3);  w3 = dot4(M[1][3], y0,y1,y2,y3);
        // ---- T2: lane transpose over bits (2,3) ----
        u2 = __shfl_xor_sync(~0u, u2, 4);  u3 = __shfl_xor_sync(~0u, u3, 4);
        w2 = __shfl_xor_sync(~0u, w2, 4);  w3 = __shfl_xor_sync(~0u, w3, 4);
        u1 = __shfl_xor_sync(~0u, u1, 8);  u3 = __shfl_xor_sync(~0u, u3, 8);
        w1 = __shfl_xor_sync(~0u, w1, 8);  w3 = __shfl_xor_sync(~0u, w3, 8);
        // ---- P2 (stages 4,5) ----
        z0 = dot4(M[2][0], u0,u1,u2,u3);  z1 = dot4(M[2][1], u0,u1,u2,u3);
        z2 = dot4(M[2][2], u0,u1,u2,u3);  z3 = dot4(M[2][3], u0,u1,u2,u3);
        y0 = dot4(M[2][0], w0,w1,w2,w3);  y1 = dot4(M[2][1], w0,w1,w2,w3);
        y2 = dot4(M[2][2], w0,w1,w2,w3);  y3 = dot4(M[2][3], w0,w1,w2,w3);
        // ---- T3: smem re-own to stride-64 combs ----
        S3[a3s]             = z0;  S3[a3s + 16]        = z1;
        S3[a3s + 32]        = z2;  S3[a3s + 48]        = z3;
        S3[1264 + a3s]      = y0;  S3[1264 + a3s + 16] = y1;
        S3[1264 + a3s + 32] = y2;  S3[1264 + a3s + 48] = y3;
        __syncthreads();
        u0 = S3[a3l];        u1 = S3[a3l + 80];
        u2 = S3[a3l + 160];  u3 = S3[a3l + 240];
        w0 = S3[1264 + a3l];       w1 = S3[1264 + a3l + 80];
        w2 = S3[1264 + a3l + 160]; w3 = S3[1264 + a3l + 240];
        // ---- P3 (stages 6,7) ----
        z0 = dot4(M[3][0], u0,u1,u2,u3);  z1 = dot4(M[3][1], u0,u1,u2,u3);
        z2 = dot4(M[3][2], u0,u1,u2,u3);  z3 = dot4(M[3][3], u0,u1,u2,u3);
        y0 = dot4(M[3][0], w0,w1,w2,w3);  y1 = dot4(M[3][1], w0,w1,w2,w3);
        y2 = dot4(M[3][2], w0,w1,w2,w3);  y3 = dot4(M[3][3], w0,w1,w2,w3);
        // ---- T4: smem re-own to stride-256 combs ----
        S4[a4s]             = z0;  S4[a4s + 66]        = z1;
        S4[a4s + 132]       = z2;  S4[a4s + 198]       = z3;
        S4[1056 + a4s]      = y0;  S4[1056 + a4s + 66] = y1;
        S4[1056 + a4s + 132]= y2;  S4[1056 + a4s + 198]= y3;
        __syncthreads();
        u0 = S4[a4l];        u1 = S4[a4l + 264];
        u2 = S4[a4l + 528];  u3 = S4[a4l + 792];
        w0 = S4[1056 + a4l];       w1 = S4[1056 + a4l + 264];
        w2 = S4[1056 + a4l + 528]; w3 = S4[1056 + a4l + 792];
        // ---- P4 (stages 8,9) + bias ----
        z0 = dot4(M[4][0], u0,u1,u2,u3) + bz0;
        z1 = dot4(M[4][1], u0,u1,u2,u3) + bz1;
        z2 = dot4(M[4][2], u0,u1,u2,u3) + bz2;
        z3 = dot4(M[4][3], u0,u1,u2,u3) + bz3;
        y0 = dot4(M[4][0], w0,w1,w2,w3) + bz0;
        y1 = dot4(M[4][1], w0,w1,w2,w3) + bz1;
        y2 = dot4(M[4][2], w0,w1,w2,w3) + bz2;
        y3 = dot4(M[4][3], w0,w1,w2,w3) + bz3;

        const int r0 = 2 * pi, r1 = 2 * pi + 1;
        {
            float* o = out + (size_t)r0 * 1024;
            o[t] = z0;  o[t + 256] = z1;  o[t + 512] = z2;  o[t + 768] = z3;
        }
        if (r1 < nrows) {
            float* o = out + (size_t)r1 * 1024;
            o[t] = y0;  o[t + 256] = y1;  o[t + 512] = y2;  o[t + 768] = y3;
        }

        pi = npi;
        A0 = NA0;  A1 = NA1;
    }
}

extern "C" void kernel_launch(void* const* d_in, const int* in_sizes, int n_in,
                              void* d_out, int out_size)
{
    const float* x  = nullptr;
    const float* tw = nullptr;
    const float* bs = nullptr;
    long long x_elems = 0;
    for (int i = 0; i < n_in; ++i) {
        if (in_sizes[i] == 20480)     tw = (const float*)d_in[i];
        else if (in_sizes[i] == 1024) bs = (const float*)d_in[i];
        else { x = (const float*)d_in[i]; x_elems = in_sizes[i]; }
    }
    const int nrows = (int)(x_elems / 1024);

    butterfly_kernel<<<GRID, TPB>>>(x, tw, bs, (float*)d_out, nrows);
}